// round 15
// baseline (speedup 1.0000x reference)
#include <cuda_runtime.h>
#include <cuda_bf16.h>
#include <math.h>
#include <stdint.h>

// Problem constants
#define BB   16
#define NN_  768
#define FF   512
#define NBB  256
#define HH   8
#define DD   64

typedef __nv_bfloat16 bf16;

__device__ __forceinline__ uint32_t smem_u32(const void* p) {
    uint32_t a;
    asm("{ .reg .u64 t; cvta.to.shared.u64 t, %1; cvt.u32.u64 %0, t; }" : "=r"(a) : "l"(p));
    return a;
}

__device__ __forceinline__ void ldsm4(uint32_t* r, uint32_t addr) {
    asm volatile("ldmatrix.sync.aligned.m8n8.x4.shared.b16 {%0,%1,%2,%3}, [%4];"
        : "=r"(r[0]), "=r"(r[1]), "=r"(r[2]), "=r"(r[3]) : "r"(addr));
}

__device__ __forceinline__ void mma16816(float* c, const uint32_t* a, const uint32_t* b) {
    asm volatile(
        "mma.sync.aligned.m16n8k16.row.col.f32.bf16.bf16.f32 "
        "{%0,%1,%2,%3}, {%4,%5,%6,%7}, {%8,%9}, {%0,%1,%2,%3};"
        : "+f"(c[0]), "+f"(c[1]), "+f"(c[2]), "+f"(c[3])
        : "r"(a[0]), "r"(a[1]), "r"(a[2]), "r"(a[3]), "r"(b[0]), "r"(b[1]));
}

__device__ __forceinline__ void split_hl(float v, bf16& h, bf16& l) {
    h = __float2bfloat16(v);
    l = __float2bfloat16(v - __bfloat162float(h));
}

__device__ __forceinline__ uint32_t packb(bf16 lo16, bf16 hi16) {
    __nv_bfloat162 t; t.x = lo16; t.y = hi16;
    return *(uint32_t*)&t;
}

__device__ __forceinline__ void cp16(uint32_t d, const void* s) {
    asm volatile("cp.async.cg.shared.global [%0], [%1], 16;" :: "r"(d), "l"(s));
}
#define CP_COMMIT() asm volatile("cp.async.commit_group;" ::: "memory")
#define CP_WAIT0()  asm volatile("cp.async.wait_group 0;" ::: "memory")
#define CP_WAIT1()  asm volatile("cp.async.wait_group 1;" ::: "memory")

// ===========================================================================
// Scratch buffers
// ===========================================================================
static const long long F_S1   = 0;
static const long long F_S2   = F_S1  + 16LL*256*768;
static const long long F_S3   = F_S2  + 16LL*768*256;
static const long long F_AIJ  = F_S3  + 16LL*768*256;
static const long long F_FG   = F_AIJ + 12288LL*512;
static const long long F_TOT  = F_FG  + 12288LL*512;

__device__ float g_f32[F_TOT];

#define PS 6291456LL

static const long long B_X1    = 0;                             static const long long SZ_X1    = 12288LL*512;
static const long long B_ZB    = B_X1    + 2*SZ_X1;             static const long long SZ_ZB    = 256LL*512;
static const long long B_WB    = B_ZB    + 2*SZ_ZB;             static const long long SZ_WB    = 1536LL*512;
static const long long B_WI    = B_WB    + 2*SZ_WB;             static const long long SZ_WI    = 1024LL*512;
static const long long B_WJ    = B_WI    + 2*SZ_WI;             static const long long SZ_WJ    = 512LL*512;
static const long long B_WFC   = B_WJ    + 2*SZ_WJ;             static const long long SZ_WFC   = 512LL*1024;
static const long long B_WM    = B_WFC   + 2*SZ_WFC;            static const long long SZ_WM    = 512LL*512;
static const long long B_WQ    = B_WM    + 2*SZ_WM;             static const long long SZ_WQ    = 1536LL*512;
static const long long B_WP    = B_WQ    + 2*SZ_WQ;             static const long long SZ_WP    = 512LL*512;
static const long long B_QKVB  = B_WP    + 2*SZ_WP;             static const long long SZ_QKVB  = 256LL*1536;
static const long long B_KVI   = B_QKVB  + 2*SZ_QKVB;           static const long long SZ_KVI   = 12288LL*1024;
static const long long B_QJ    = B_KVI   + 2*SZ_KVI;            static const long long SZ_QJ    = 12288LL*512;
static const long long B_S1    = B_QJ    + 2*SZ_QJ;             static const long long SZ_S1    = 16LL*256*768;
static const long long B_VIT   = B_S1    + 2*SZ_S1;             static const long long SZ_VIT   = 16LL*512*768;
static const long long B_AIB1  = B_VIT   + 2*SZ_VIT;            static const long long SZ_AIB1  = 16LL*256*512;
static const long long B_AIB1T = B_AIB1  + 2*SZ_AIB1;           static const long long SZ_AIB1T = 16LL*512*256;
static const long long B_VBT   = B_AIB1T + 2*SZ_AIB1T;          static const long long SZ_VBT   = 512LL*256;
static const long long B_S2    = B_VBT   + 2*SZ_VBT;            static const long long SZ_S2    = 16LL*768*256;
static const long long B_S3    = B_S2    + 2*SZ_S2;             static const long long SZ_S3    = 16LL*768*256;
static const long long B_CAT   = B_S3    + 2*SZ_S3;             static const long long SZ_CAT   = 12288LL*1024;
static const long long B_HB    = B_CAT   + 2*SZ_CAT;            static const long long SZ_HB    = 12288LL*512;
static const long long B_QKVH  = B_HB    + 2*SZ_HB;
static const long long B_VT    = B_QKVH  + 6*PS;
static const long long B_HC    = B_VT    + 2*PS;                static const long long SZ_HC    = 12288LL*512;
static const long long B_TOT   = B_HC    + 2*SZ_HC;

__device__ bf16 g_bf[B_TOT];

// ===========================================================================
// GEMM descriptor + multi-GEMM dispatch (wave packing) + epilogue transposes
// ===========================================================================
#define KT 32
#define SMP 40
#define HALFB  (128 * SMP * 2)
#define STGB   (4 * HALFB)
#define GEMM_SMEM (2 * STGB)

struct GDesc {
    const bf16 *Ahi, *Alo, *Bhi, *Blo;
    int lda, ldb;
    long long sA, sB;
    float* C; int ldc; long long sC;
    float alpha; const float* bias;
    int beta, act;
    bf16 *Chi, *Clo; int wr_f32;
    const float *Gz, *Gf; int qkv;
    int ldco; long long sCo;
    // epilogue transpose: 0=off, 1=per-batch transpose cols>=tcol0 -> T[(col-tcol0)*ldt+row],
    // 2=v_i head mapping cols>=512 -> T[(b*512 + col-512)*768 + n]
    bf16 *Thi, *Tlo; int tmode, tcol0, ldt; long long sT;
    int M, N, K, gx, gy, batch;
};

__device__ __forceinline__ void gemm_body(const GDesc& d, int bxi, int byi, int bzi,
                                          bf16* smbuf, int tid)
{
    const uint32_t sbase = smem_u32(smbuf);
    const int lane = tid & 31, wid = tid >> 5;
    const int m0 = byi * 128, n0 = bxi * 128;
    const int wm = wid & 3, wn = wid >> 2;
    const int m0w = wm * 32, n0w = wn * 64;

    const bf16* Ah = d.Ahi + bzi * d.sA + (size_t)m0 * d.lda;
    const bf16* Al = d.Alo + bzi * d.sA + (size_t)m0 * d.lda;
    const bf16* Bh = d.Bhi + bzi * d.sB + (size_t)n0 * d.ldb;
    const bf16* Bl = d.Blo + bzi * d.sB + (size_t)n0 * d.ldb;

    float acc[2][8][4];
    #pragma unroll
    for (int i = 0; i < 2; ++i)
        #pragma unroll
        for (int j = 0; j < 8; ++j)
            #pragma unroll
            for (int q = 0; q < 4; ++q) acc[i][j][q] = 0.0f;

    const int nk = d.K / KT;
    const int lda = d.lda, ldb = d.ldb;

    auto load_stage = [&](int st, int k0) {
        const uint32_t sb0 = sbase + st * STGB;
        #pragma unroll
        for (int it = 0; it < 2; ++it) {
            int cid = tid + it * 256;
            int row = cid >> 2;
            int c   = (cid & 3) * 8;
            uint32_t off = (uint32_t)(row * SMP + c) * 2;
            cp16(sb0 + off,              Ah + (size_t)row * lda + k0 + c);
            cp16(sb0 + HALFB + off,      Al + (size_t)row * lda + k0 + c);
            cp16(sb0 + 2 * HALFB + off,  Bh + (size_t)row * ldb + k0 + c);
            cp16(sb0 + 3 * HALFB + off,  Bl + (size_t)row * ldb + k0 + c);
        }
    };

    load_stage(0, 0);
    CP_COMMIT();

    for (int i = 0; i < nk; ++i) {
        if (i + 1 < nk) { load_stage((i + 1) & 1, (i + 1) * KT); CP_COMMIT(); }
        if (i + 1 < nk) CP_WAIT1(); else CP_WAIT0();
        __syncthreads();

        const uint32_t sa  = sbase + (i & 1) * STGB;
        const uint32_t sbm = sa + 2 * HALFB;

        #pragma unroll
        for (int kk = 0; kk < 2; ++kk) {
            uint32_t ah[2][4], al[2][4];
            #pragma unroll
            for (int mi = 0; mi < 2; ++mi) {
                uint32_t addr = sa + ((m0w + mi * 16 + (lane & 15)) * SMP
                                      + kk * 16 + (lane >> 4) * 8) * 2;
                ldsm4(ah[mi], addr);
                ldsm4(al[mi], addr + HALFB);
            }
            #pragma unroll
            for (int g = 0; g < 4; ++g) {
                uint32_t bh[4], bl[4];
                int q = lane >> 3;
                int row = n0w + g * 16 + ((q >> 1) << 3) + (lane & 7);
                int kc  = kk * 16 + (q & 1) * 8;
                uint32_t addr = sbm + (row * SMP + kc) * 2;
                ldsm4(bh, addr);
                ldsm4(bl, addr + HALFB);
                #pragma unroll
                for (int mi = 0; mi < 2; ++mi) {
                    mma16816(acc[mi][g * 2 + 0], ah[mi], bh + 0);
                    mma16816(acc[mi][g * 2 + 0], ah[mi], bl + 0);
                    mma16816(acc[mi][g * 2 + 0], al[mi], bh + 0);
                    mma16816(acc[mi][g * 2 + 1], ah[mi], bh + 2);
                    mma16816(acc[mi][g * 2 + 1], ah[mi], bl + 2);
                    mma16816(acc[mi][g * 2 + 1], al[mi], bh + 2);
                }
            }
        }
        __syncthreads();
    }

    const int rb = m0 + m0w + (lane >> 2);
    const int cb = n0 + n0w + (lane & 3) * 2;

    if (d.qkv) {
        #pragma unroll
        for (int mi = 0; mi < 2; ++mi) {
            #pragma unroll
            for (int ni = 0; ni < 8; ++ni) {
                const int col = cb + ni * 8;
                const int t = col >> 9, cw = col & 511;
                const int hh2 = cw >> 6, dd2 = cw & 63;
                bf16* ph = d.Chi + (long long)t * 2 * PS;
                bf16* vth = d.Chi + 6 * PS;     // VT hi plane
                #pragma unroll
                for (int h2 = 0; h2 < 2; ++h2) {
                    const int row = rb + mi * 16 + h2 * 8;
                    const int b2 = row / 768, n2 = row - b2 * 768;
                    float v0 = acc[mi][ni][h2 * 2 + 0] * d.alpha;
                    float v1 = acc[mi][ni][h2 * 2 + 1] * d.alpha;
                    bf16 h0, l0, h1, l1;
                    split_hl(v0, h0, l0); split_hl(v1, h1, l1);
                    if (t == 2) {
                        // write V transposed: [bh, 64, 768]
                        size_t tix = ((size_t)((b2 * 8 + hh2) * 64 + dd2)) * 768 + n2;
                        vth[tix] = h0;            vth[PS + tix] = l0;
                        vth[tix + 768] = h1;      vth[PS + tix + 768] = l1;
                    } else {
                        size_t ix = ((size_t)((b2 * 8 + hh2) * 768 + n2)) * 64 + dd2;
                        *(uint32_t*)(ph + ix) = packb(h0, h1);
                        *(uint32_t*)(ph + PS + ix) = packb(l0, l1);
                    }
                }
            }
        }
        return;
    }

    float* Cb = d.C + bzi * d.sC;
    bf16* Chb = d.Chi ? d.Chi + bzi * d.sCo : nullptr;
    bf16* Clb = d.Clo ? d.Clo + bzi * d.sCo : nullptr;
    bf16* Thb = d.Thi ? d.Thi + bzi * d.sT : nullptr;
    bf16* Tlb = d.Tlo ? d.Tlo + bzi * d.sT : nullptr;

    #pragma unroll
    for (int mi = 0; mi < 2; ++mi) {
        #pragma unroll
        for (int ni = 0; ni < 8; ++ni) {
            const int col = cb + ni * 8;
            if (col >= d.N) continue;
            float b0 = d.bias ? d.bias[col] : 0.0f;
            float b1 = d.bias ? d.bias[col + 1] : 0.0f;
            #pragma unroll
            for (int h = 0; h < 2; ++h) {
                const int row = rb + mi * 16 + h * 8;
                size_t ix = (size_t)row * d.ldc + col;
                float v0 = acc[mi][ni][h * 2 + 0] * d.alpha + b0;
                float v1 = acc[mi][ni][h * 2 + 1] * d.alpha + b1;
                if (d.beta) { v0 += Cb[ix]; v1 += Cb[ix + 1]; }
                if (d.act == 1) {
                    v0 = 1.0f / (1.0f + __expf(-v0));
                    v1 = 1.0f / (1.0f + __expf(-v1));
                } else if (d.act == 2) {
                    v0 = fmaxf(0.0f, d.Gz[ix] + v0 * d.Gf[ix]);
                    v1 = fmaxf(0.0f, d.Gz[ix + 1] + v1 * d.Gf[ix + 1]);
                }
                if (d.wr_f32) { Cb[ix] = v0; Cb[ix + 1] = v1; }
                bf16 h0, l0, h1, l1;
                split_hl(v0, h0, l0); split_hl(v1, h1, l1);
                if (Chb) {
                    size_t ixo = (size_t)row * d.ldco + col;
                    Chb[ixo] = h0; Clb[ixo] = l0;
                    Chb[ixo + 1] = h1; Clb[ixo + 1] = l1;
                }
                if (d.tmode == 1) {
                    if (col >= d.tcol0) {
                        size_t tix = (size_t)(col - d.tcol0) * d.ldt + row;
                        Thb[tix] = h0; Tlb[tix] = l0;
                        Thb[tix + d.ldt] = h1; Tlb[tix + d.ldt] = l1;
                    }
                } else if (d.tmode == 2) {
                    if (col >= 512) {
                        int b2 = row / 768, n2 = row - b2 * 768;
                        size_t tix = ((size_t)b2 * 512 + (col - 512)) * 768 + n2;
                        d.Thi[tix] = h0; d.Tlo[tix] = l0;
                        d.Thi[tix + 768] = h1; d.Tlo[tix + 768] = l1;
                    }
                }
            }
        }
    }
}

__global__ void __launch_bounds__(256, 2)
mma_multi(GDesc d0, GDesc d1, GDesc d2, int n1, int n2)
{
    extern __shared__ bf16 smbuf[];
    const GDesc& d = (blockIdx.x < (unsigned)n1) ? d0
                   : ((blockIdx.x < (unsigned)n2) ? d1 : d2);
    int local = (blockIdx.x < (unsigned)n1) ? blockIdx.x
              : ((blockIdx.x < (unsigned)n2) ? blockIdx.x - n1 : blockIdx.x - n2);
    int per = d.gx * d.gy;
    int bzi = local / per;
    int rem = local - bzi * per;
    int byi = rem / d.gx;
    int bxi = rem - byi * d.gx;
    gemm_body(d, bxi, byi, bzi, smbuf, threadIdx.x);
}

// ===========================================================================
// Fused flash MHSA — cp.async double-buffered K/V (verified R13)
// ===========================================================================
#define QPITCH 72
#define VPITCH 136
#define QPL (128 * QPITCH)
#define VPL (64 * VPITCH)
#define FL_SMEM ((6 * QPL + 4 * VPL) * 2)

__global__ void __launch_bounds__(256)
flash_mhsa(const bf16* __restrict__ Qhp, const bf16* __restrict__ Qlp,
           const bf16* __restrict__ Khp, const bf16* __restrict__ Klp,
           const bf16* __restrict__ VThp, const bf16* __restrict__ VTlp,
           bf16* __restrict__ Ohi, bf16* __restrict__ Olo)
{
    extern __shared__ char sm[];
    const uint32_t base = smem_u32(sm);
    const uint32_t uQ = base;
    const uint32_t uK0 = base + 2 * QPL * 2;
    const uint32_t uV0 = base + 6 * QPL * 2;
    const uint32_t KSTG = 2 * QPL * 2;
    const uint32_t VSTG = 2 * VPL * 2;
    const uint32_t QHALF = QPL * 2;
    const uint32_t VHALF = VPL * 2;

    const int bh = blockIdx.x;
    const int mb = blockIdx.y;
    const int tid = threadIdx.x, lane = tid & 31, wid = tid >> 5;

    const size_t qoff = (size_t)bh * 768 * 64 + (size_t)mb * 128 * 64;
    const size_t koff = (size_t)bh * 768 * 64;
    const size_t voff = (size_t)bh * 64 * 768;

    auto load_kv = [&](int st, int it) {
        const uint32_t uk = uK0 + st * KSTG;
        const uint32_t uv = uV0 + st * VSTG;
        for (int i = tid; i < 1024; i += 256) {
            int r = i >> 3, c = (i & 7) * 8;
            uint32_t dst = uk + (uint32_t)(r * QPITCH + c) * 2;
            cp16(dst,          Khp + koff + (size_t)(it * 128 + r) * 64 + c);
            cp16(dst + QHALF,  Klp + koff + (size_t)(it * 128 + r) * 64 + c);
        }
        for (int i = tid; i < 1024; i += 256) {
            int r = i >> 4, c = (i & 15) * 8;
            uint32_t dst = uv + (uint32_t)(r * VPITCH + c) * 2;
            cp16(dst,          VThp + voff + (size_t)r * 768 + it * 128 + c);
            cp16(dst + VHALF,  VTlp + voff + (size_t)r * 768 + it * 128 + c);
        }
    };

    for (int i = tid; i < 1024; i += 256) {
        int r = i >> 3, c = (i & 7) * 8;
        uint32_t dst = uQ + (uint32_t)(r * QPITCH + c) * 2;
        cp16(dst,          Qhp + qoff + (size_t)r * 64 + c);
        cp16(dst + QHALF,  Qlp + qoff + (size_t)r * 64 + c);
    }
    load_kv(0, 0);
    CP_COMMIT();

    float m_r[2] = {-1e30f, -1e30f};
    float l_r[2] = {0.0f, 0.0f};
    float oacc[8][4];
    #pragma unroll
    for (int j = 0; j < 8; ++j)
        #pragma unroll
        for (int q = 0; q < 4; ++q) oacc[j][q] = 0.0f;

    for (int it = 0; it < 6; ++it) {
        if (it + 1 < 6) { load_kv((it + 1) & 1, it + 1); CP_COMMIT(); }
        if (it + 1 < 6) CP_WAIT1(); else CP_WAIT0();
        __syncthreads();

        const uint32_t uK = uK0 + (it & 1) * KSTG;
        const uint32_t uV = uV0 + (it & 1) * VSTG;

        float sacc[16][4];
        #pragma unroll
        for (int g = 0; g < 16; ++g)
            #pragma unroll
            for (int q = 0; q < 4; ++q) sacc[g][q] = 0.0f;

        #pragma unroll
        for (int kk = 0; kk < 4; ++kk) {
            uint32_t ah[4], al[4];
            uint32_t addr = uQ + ((wid * 16 + (lane & 15)) * QPITCH
                                  + kk * 16 + (lane >> 4) * 8) * 2;
            ldsm4(ah, addr);
            ldsm4(al, addr + QHALF);
            #pragma unroll
            for (int g = 0; g < 8; ++g) {
                uint32_t bh4[4], bl4[4];
                int q = lane >> 3;
                int row = g * 16 + ((q >> 1) << 3) + (lane & 7);
                int kc  = kk * 16 + (q & 1) * 8;
                uint32_t ba = uK + (row * QPITCH + kc) * 2;
                ldsm4(bh4, ba);
                ldsm4(bl4, ba + QHALF);
                mma16816(sacc[g * 2 + 0], ah, bh4 + 0);
                mma16816(sacc[g * 2 + 0], ah, bl4 + 0);
                mma16816(sacc[g * 2 + 0], al, bh4 + 0);
                mma16816(sacc[g * 2 + 1], ah, bh4 + 2);
                mma16816(sacc[g * 2 + 1], ah, bl4 + 2);
                mma16816(sacc[g * 2 + 1], al, bh4 + 2);
            }
        }

        float mx0 = -1e30f, mx1 = -1e30f;
        #pragma unroll
        for (int g = 0; g < 16; ++g) {
            sacc[g][0] *= 0.125f; sacc[g][1] *= 0.125f;
            sacc[g][2] *= 0.125f; sacc[g][3] *= 0.125f;
            mx0 = fmaxf(mx0, fmaxf(sacc[g][0], sacc[g][1]));
            mx1 = fmaxf(mx1, fmaxf(sacc[g][2], sacc[g][3]));
        }
        #pragma unroll
        for (int d = 1; d <= 2; d <<= 1) {
            mx0 = fmaxf(mx0, __shfl_xor_sync(0xffffffffu, mx0, d));
            mx1 = fmaxf(mx1, __shfl_xor_sync(0xffffffffu, mx1, d));
        }
        float mn0 = fmaxf(m_r[0], mx0), mn1 = fmaxf(m_r[1], mx1);
        float al0 = __expf(m_r[0] - mn0), al1 = __expf(m_r[1] - mn1);
        float sum0 = 0.0f, sum1 = 0.0f;
        #pragma unroll
        for (int g = 0; g < 16; ++g) {
            sacc[g][0] = __expf(sacc[g][0] - mn0);
            sacc[g][1] = __expf(sacc[g][1] - mn0);
            sacc[g][2] = __expf(sacc[g][2] - mn1);
            sacc[g][3] = __expf(sacc[g][3] - mn1);
            sum0 += sacc[g][0] + sacc[g][1];
            sum1 += sacc[g][2] + sacc[g][3];
        }
        #pragma unroll
        for (int d = 1; d <= 2; d <<= 1) {
            sum0 += __shfl_xor_sync(0xffffffffu, sum0, d);
            sum1 += __shfl_xor_sync(0xffffffffu, sum1, d);
        }
        l_r[0] = l_r[0] * al0 + sum0;
        l_r[1] = l_r[1] * al1 + sum1;
        m_r[0] = mn0; m_r[1] = mn1;
        #pragma unroll
        for (int j = 0; j < 8; ++j) {
            oacc[j][0] *= al0; oacc[j][1] *= al0;
            oacc[j][2] *= al1; oacc[j][3] *= al1;
        }

        #pragma unroll
        for (int s = 0; s < 8; ++s) {
            uint32_t pah[4], pal[4];
            {
                bf16 h0, l0, h1, l1;
                split_hl(sacc[2*s][0], h0, l0); split_hl(sacc[2*s][1], h1, l1);
                pah[0] = packb(h0, h1); pal[0] = packb(l0, l1);
                split_hl(sacc[2*s][2], h0, l0); split_hl(sacc[2*s][3], h1, l1);
                pah[1] = packb(h0, h1); pal[1] = packb(l0, l1);
                split_hl(sacc[2*s+1][0], h0, l0); split_hl(sacc[2*s+1][1], h1, l1);
                pah[2] = packb(h0, h1); pal[2] = packb(l0, l1);
                split_hl(sacc[2*s+1][2], h0, l0); split_hl(sacc[2*s+1][3], h1, l1);
                pah[3] = packb(h0, h1); pal[3] = packb(l0, l1);
            }
            #pragma unroll
            for (int g = 0; g < 4; ++g) {
                uint32_t bh4[4], bl4[4];
                int q = lane >> 3;
                int row = g * 16 + ((q >> 1) << 3) + (lane & 7);
                int kc  = s * 16 + (q & 1) * 8;
                uint32_t ba = uV + (row * VPITCH + kc) * 2;
                ldsm4(bh4, ba);
                ldsm4(bl4, ba + VHALF);
                mma16816(oacc[g * 2 + 0], pah, bh4 + 0);
                mma16816(oacc[g * 2 + 0], pah, bl4 + 0);
                mma16816(oacc[g * 2 + 0], pal, bh4 + 0);
                mma16816(oacc[g * 2 + 1], pah, bh4 + 2);
                mma16816(oacc[g * 2 + 1], pah, bl4 + 2);
                mma16816(oacc[g * 2 + 1], pal, bh4 + 2);
            }
        }
        __syncthreads();
    }

    const float inv0 = 1.0f / l_r[0], inv1 = 1.0f / l_r[1];
    const int b = bh >> 3, h = bh & 7;
    const int n0g = mb * 128 + wid * 16 + (lane >> 2);
    #pragma unroll
    for (int j = 0; j < 8; ++j) {
        const int d = j * 8 + (lane & 3) * 2;
        {
            size_t ix = ((size_t)(b * 768 + n0g) * 512) + h * 64 + d;
            bf16 h0, l0, h1, l1;
            split_hl(oacc[j][0] * inv0, h0, l0);
            split_hl(oacc[j][1] * inv0, h1, l1);
            *(uint32_t*)(Ohi + ix) = packb(h0, h1);
            *(uint32_t*)(Olo + ix) = packb(l0, l1);
        }
        {
            size_t ix = ((size_t)(b * 768 + n0g + 8) * 512) + h * 64 + d;
            bf16 h0, l0, h1, l1;
            split_hl(oacc[j][2] * inv1, h0, l0);
            split_hl(oacc[j][3] * inv1, h1, l1);
            *(uint32_t*)(Ohi + ix) = packb(h0, h1);
            *(uint32_t*)(Olo + ix) = packb(l0, l1);
        }
    }
}

// ===========================================================================
// Conversion / transform kernels
// ===========================================================================
struct CTable {
    const float* src[3];
    bf16* hi[3];
    bf16* lo[3];
    int lds[3], ldd[3], C[3];
    long long n1, n2;
};

__global__ void conv_batch(CTable ct)
{
    long long i = (long long)blockIdx.x * blockDim.x + threadIdx.x;
    int e; long long local;
    if (i < ct.n1) { e = 0; local = i; }
    else if (i < ct.n2) { e = 1; local = i - ct.n1; }
    else { e = 2; local = i - ct.n2; }
    int c4 = ct.C[e] / 4;
    int r = (int)(local / c4), c = (int)(local % c4) * 4;
    float4 v = *(const float4*)(ct.src[e] + (size_t)r * ct.lds[e] + c);
    bf16 h0, h1, h2, h3, l0, l1, l2, l3;
    split_hl(v.x, h0, l0); split_hl(v.y, h1, l1);
    split_hl(v.z, h2, l2); split_hl(v.w, h3, l3);
    size_t o = (size_t)r * ct.ldd[e] + c;
    bf16* hi = ct.hi[e]; bf16* lo = ct.lo[e];
    hi[o] = h0; hi[o+1] = h1; hi[o+2] = h2; hi[o+3] = h3;
    lo[o] = l0; lo[o+1] = l1; lo[o+2] = l2; lo[o+3] = l3;
}

struct TTable {
    const float* src[8];
    bf16* hi[8];
    bf16* lo[8];
    int lds[8];
    int ldd[8];
    int C[8];
};

__global__ void tconv_batch(TTable tt)
{
    __shared__ float t[32][33];
    const int e = blockIdx.z;
    const int c0 = blockIdx.x * 32;
    if (c0 >= tt.C[e]) return;
    const float* s = tt.src[e];
    const int lds = tt.lds[e], ldd = tt.ldd[e];
    const int r0 = blockIdx.y * 32;
    int tx = threadIdx.x, ty = threadIdx.y;
    #pragma unroll
    for (int i = 0; i < 32; i += 8) {
        int r = r0 + ty + i, c = c0 + tx;
        t[ty + i][tx] = s[(size_t)r * lds + c];
    }
    __syncthreads();
    bf16* hb = tt.hi[e];
    bf16* lb = tt.lo[e];
    #pragma unroll
    for (int i = 0; i < 32; i += 8) {
        int c = c0 + ty + i, r = r0 + tx;
        bf16 h, l; split_hl(t[tx][ty + i], h, l);
        hb[(size_t)c * ldd + r] = h;
        lb[(size_t)c * ldd + r] = l;
    }
}

__device__ __forceinline__ void softmax_body(const float* p, bf16* ph, bf16* pl, int L, int t)
{
    __shared__ float red[256];
    const int nv = L >> 8;
    float v[3];
    float mx = -1e30f;
    for (int j = 0; j < nv; ++j) {
        v[j] = p[t + (j << 8)];
        mx = fmaxf(mx, v[j]);
    }
    red[t] = mx; __syncthreads();
    for (int s = 128; s > 0; s >>= 1) { if (t < s) red[t] = fmaxf(red[t], red[t + s]); __syncthreads(); }
    mx = red[0]; __syncthreads();

    float e[3];
    float sum = 0.0f;
    for (int j = 0; j < nv; ++j) {
        e[j] = __expf(v[j] - mx);
        sum += e[j];
    }
    red[t] = sum; __syncthreads();
    for (int s = 128; s > 0; s >>= 1) { if (t < s) red[t] += red[t + s]; __syncthreads(); }
    const float inv = 1.0f / red[0];
    for (int j = 0; j < nv; ++j) {
        float w = e[j] * inv;
        bf16 h, l; split_hl(w, h, l);
        ph[t + (j << 8)] = h; pl[t + (j << 8)] = l;
    }
}

__global__ void __launch_bounds__(256)
softmax_hilo(const float* __restrict__ src, bf16* __restrict__ hi, bf16* __restrict__ lo, int L)
{
    softmax_body(src + (size_t)blockIdx.x * L, hi + (size_t)blockIdx.x * L,
                 lo + (size_t)blockIdx.x * L, L, threadIdx.x);
}

__global__ void __launch_bounds__(256)
softmax2(const float* __restrict__ s1, bf16* __restrict__ h1, bf16* __restrict__ l1,
         int L1, int nb1,
         const float* __restrict__ s2, bf16* __restrict__ h2, bf16* __restrict__ l2, int L2)
{
    if (blockIdx.x < (unsigned)nb1) {
        size_t o = (size_t)blockIdx.x * L1;
        softmax_body(s1 + o, h1 + o, l1 + o, L1, threadIdx.x);
    } else {
        size_t o = (size_t)(blockIdx.x - nb1) * L2;
        softmax_body(s2 + o, h2 + o, l2 + o, L2, threadIdx.x);
    }
}

// ===========================================================================
// Host side
// ===========================================================================
static GDesc mk(int M, int N, int K,
                const bf16* Ah, const bf16* Al, int lda, long long sA,
                const bf16* Bh, const bf16* Bl, int ldb, long long sB,
                float* C, int ldc, long long sC, int batch,
                float alpha, const float* bias, int beta, int act,
                bf16* Chi, bf16* Clo, int wr_f32,
                const float* Gz = nullptr, const float* Gf = nullptr, int qkv = 0,
                int ldco = -1, long long sCo = -1,
                bf16* Thi = nullptr, bf16* Tlo = nullptr, int tmode = 0,
                int tcol0 = 0, int ldt = 0, long long sT = 0)
{
    GDesc d;
    d.Ahi = Ah; d.Alo = Al; d.Bhi = Bh; d.Blo = Bl;
    d.lda = lda; d.ldb = ldb; d.sA = sA; d.sB = sB;
    d.C = C; d.ldc = ldc; d.sC = sC;
    d.alpha = alpha; d.bias = bias; d.beta = beta; d.act = act;
    d.Chi = Chi; d.Clo = Clo; d.wr_f32 = wr_f32;
    d.Gz = Gz; d.Gf = Gf; d.qkv = qkv;
    d.ldco = (ldco < 0) ? ldc : ldco;
    d.sCo = (sCo < 0) ? sC : sCo;
    d.Thi = Thi; d.Tlo = Tlo; d.tmode = tmode; d.tcol0 = tcol0; d.ldt = ldt; d.sT = sT;
    d.M = M; d.N = N; d.K = K;
    d.gx = (N + 127) / 128; d.gy = M / 128; d.batch = batch;
    return d;
}
static inline int nblk(const GDesc& d) { return d.gx * d.gy * d.batch; }

static void launch1(const GDesc& a) {
    int n = nblk(a);
    mma_multi<<<n, 256, GEMM_SMEM>>>(a, a, a, n, n);
}
static void launch2(const GDesc& a, const GDesc& b) {
    int na = nblk(a), nb = nblk(b);
    mma_multi<<<na + nb, 256, GEMM_SMEM>>>(a, b, b, na, na + nb);
}
static void launch3(const GDesc& a, const GDesc& b, const GDesc& c) {
    int na = nblk(a), nb = nblk(b), nc = nblk(c);
    mma_multi<<<na + nb + nc, 256, GEMM_SMEM>>>(a, b, c, na, na + nb);
}

extern "C" void kernel_launch(void* const* d_in, const int* in_sizes, int n_in,
                              void* d_out, int out_size)
{
    (void)in_sizes; (void)n_in; (void)out_size;

    cudaFuncSetAttribute(flash_mhsa, cudaFuncAttributeMaxDynamicSharedMemorySize, FL_SMEM);
    cudaFuncSetAttribute(mma_multi, cudaFuncAttributeMaxDynamicSharedMemorySize, GEMM_SMEM);

    float* F = nullptr; bf16* Bf = nullptr;
    cudaGetSymbolAddress((void**)&F, g_f32);
    cudaGetSymbolAddress((void**)&Bf, g_bf);

    const float* x1     = (const float*)d_in[0];
    const float* x2     = (const float*)d_in[1];
    const float* zb     = (const float*)d_in[2];
    const float* Wqkv_i = (const float*)d_in[3];
    const float* Wqkv_j = (const float*)d_in[4];
    const float* Wqkv_b = (const float*)d_in[5];
    const float* W_f    = (const float*)d_in[6];
    const float* b_f    = (const float*)d_in[7];
    const float* W_m    = (const float*)d_in[8];
    const float* b_m    = (const float*)d_in[9];
    const float* W_QKV  = (const float*)d_in[10];
    const float* W_proj = (const float*)d_in[11];
    const float* b_proj = (const float*)d_in[12];
    float* out = (float*)d_out;

    const float scale = 0.044194173824159216f;
    const int   BN    = BB * NN_;

    #define HI(X) (Bf + (X))
    #define LO(X, SZ) (Bf + (X) + (SZ))

    bf16* QKVH = Bf + B_QKVH;
    bf16* VT   = Bf + B_VT;

    // ---- input conversions ----
    {
        CTable ct;
        ct.src[0] = x1; ct.hi[0] = HI(B_X1);        ct.lo[0] = LO(B_X1, SZ_X1);        ct.lds[0] = 512; ct.ldd[0] = 512;  ct.C[0] = 512;
        ct.src[1] = x2; ct.hi[1] = HI(B_CAT) + 512; ct.lo[1] = LO(B_CAT, SZ_CAT) + 512; ct.lds[1] = 512; ct.ldd[1] = 1024; ct.C[1] = 512;
        ct.src[2] = zb; ct.hi[2] = HI(B_ZB);        ct.lo[2] = LO(B_ZB, SZ_ZB);        ct.lds[2] = 512; ct.ldd[2] = 512;  ct.C[2] = 512;
        ct.n1 = 12288LL * 128;
        ct.n2 = ct.n1 + 12288LL * 128;
        long long tot = ct.n2 + 256LL * 128;
        conv_batch<<<(unsigned)((tot + 255) / 256), 256>>>(ct);
    }

    // ---- all weight transposes in ONE batched launch ----
    {
        TTable tt;
        tt.src[0] = Wqkv_b;           tt.hi[0] = HI(B_WB);        tt.lo[0] = LO(B_WB, SZ_WB);         tt.lds[0] = 1536; tt.ldd[0] = 512;  tt.C[0] = 1536;
        tt.src[1] = Wqkv_i + 512;     tt.hi[1] = HI(B_WI);        tt.lo[1] = LO(B_WI, SZ_WI);         tt.lds[1] = 1536; tt.ldd[1] = 512;  tt.C[1] = 1024;
        tt.src[2] = Wqkv_j;           tt.hi[2] = HI(B_WJ);        tt.lo[2] = LO(B_WJ, SZ_WJ);         tt.lds[2] = 1536; tt.ldd[2] = 512;  tt.C[2] = 512;
        tt.src[3] = W_f;              tt.hi[3] = HI(B_WFC);       tt.lo[3] = LO(B_WFC, SZ_WFC);       tt.lds[3] = 512;  tt.ldd[3] = 1024; tt.C[3] = 512;
        tt.src[4] = W_f + 512LL*512;  tt.hi[4] = HI(B_WFC) + 512; tt.lo[4] = LO(B_WFC, SZ_WFC) + 512; tt.lds[4] = 512;  tt.ldd[4] = 1024; tt.C[4] = 512;
        tt.src[5] = W_m;              tt.hi[5] = HI(B_WM);        tt.lo[5] = LO(B_WM, SZ_WM);         tt.lds[5] = 512;  tt.ldd[5] = 512;  tt.C[5] = 512;
        tt.src[6] = W_QKV;            tt.hi[6] = HI(B_WQ);        tt.lo[6] = LO(B_WQ, SZ_WQ);         tt.lds[6] = 1536; tt.ldd[6] = 512;  tt.C[6] = 1536;
        tt.src[7] = W_proj;           tt.hi[7] = HI(B_WP);        tt.lo[7] = LO(B_WP, SZ_WP);         tt.lds[7] = 512;  tt.ldd[7] = 512;  tt.C[7] = 512;
        tconv_batch<<<dim3(1536/32, 512/32, 8), dim3(32, 8)>>>(tt);
    }

    // ---- Group A: G1 + G2 + G3 (epilogue-fused v_b / v_i transposes) ----
    GDesc g1 = mk(256, 1536, 512, HI(B_ZB), LO(B_ZB, SZ_ZB), 512, 0, HI(B_WB), LO(B_WB, SZ_WB), 512, 0,
                  F, 1536, 0, 1, 0.2f, nullptr, 0, 0, HI(B_QKVB), LO(B_QKVB, SZ_QKVB), 0,
                  nullptr, nullptr, 0, -1, -1,
                  HI(B_VBT), LO(B_VBT, SZ_VBT), 1, 1024, 256, 0);
    GDesc g2 = mk(BN, 1024, 512, HI(B_X1), LO(B_X1, SZ_X1), 512, 0, HI(B_WI), LO(B_WI, SZ_WI), 512, 0,
                  F, 1024, 0, 1, 1.0f, nullptr, 0, 0, HI(B_KVI), LO(B_KVI, SZ_KVI), 0,
                  nullptr, nullptr, 0, -1, -1,
                  HI(B_VIT), LO(B_VIT, SZ_VIT), 2, 0, 0, 0);
    GDesc g3 = mk(BN, 512, 512, HI(B_CAT) + 512, LO(B_CAT, SZ_CAT) + 512, 1024, 0,
                  HI(B_WJ), LO(B_WJ, SZ_WJ), 512, 0,
                  F, 512, 0, 1, 1.0f, nullptr, 0, 0, HI(B_QJ), LO(B_QJ, SZ_QJ), 0);
    launch3(g2, g3, g1);

    // ---- Group B: G4 + G6 ----
    GDesc g4 = mk(256, 768, 512, HI(B_QKVB), LO(B_QKVB, SZ_QKVB), 1536, 0,
                  HI(B_KVI), LO(B_KVI, SZ_KVI), 1024, 768LL*1024,
                  F + F_S1, 768, 256LL*768, BB, scale, nullptr, 0, 0, nullptr, nullptr, 1);
    GDesc g6 = mk(768, 256, 512, HI(B_QJ), LO(B_QJ, SZ_QJ), 512, 768LL*512,
                  HI(B_QKVB) + 512, LO(B_QKVB, SZ_QKVB) + 512, 1536, 0,
                  F + F_S2, 256, 768LL*256, BB, scale, nullptr, 0, 0, nullptr, nullptr, 1);
    launch2(g4, g6);

    // ---- merged softmax S1 + S2 ----
    softmax2<<<BB*256 + BB*768, 256>>>(
        F + F_S1, HI(B_S1), LO(B_S1, SZ_S1), 768, BB*256,
        F + F_S2, HI(B_S2), LO(B_S2, SZ_S2), 256);

    // ---- Group C: G5 (epilogue-fused AIB1T) + G7 ----
    GDesc g5 = mk(256, 512, 768, HI(B_S1), LO(B_S1, SZ_S1), 768, 256LL*768,
                  HI(B_VIT), LO(B_VIT, SZ_VIT), 768, 512LL*768,
                  F, 512, 256LL*512, BB, 1.0f, nullptr, 0, 0, HI(B_AIB1), LO(B_AIB1, SZ_AIB1), 0,
                  nullptr, nullptr, 0, -1, -1,
                  HI(B_AIB1T), LO(B_AIB1T, SZ_AIB1T), 1, 0, 256, 512LL*256);
    GDesc g7 = mk(768, 512, 256, HI(B_S2), LO(B_S2, SZ_S2), 256, 768LL*256,
                  HI(B_VBT), LO(B_VBT, SZ_VBT), 256, 0,
                  F + F_AIJ, 512, 768LL*512, BB, 0.5f, nullptr, 0, 0, nullptr, nullptr, 1);
    launch2(g5, g7);

    // ---- G8 + softmax ----
    launch1(mk(768, 256, 512, HI(B_X1), LO(B_X1, SZ_X1), 512, 768LL*512,
               HI(B_AIB1), LO(B_AIB1, SZ_AIB1), 512, 256LL*512,
               F + F_S3, 256, 768LL*256, BB, scale, nullptr, 0, 0, nullptr, nullptr, 1));
    softmax_hilo<<<BB*768, 256>>>(F + F_S3, HI(B_S3), LO(B_S3, SZ_S3), 256);

    // ---- G9 ----
    launch1(mk(768, 512, 256, HI(B_S3), LO(B_S3, SZ_S3), 256, 768LL*256,
               HI(B_AIB1T), LO(B_AIB1T, SZ_AIB1T), 256, 512LL*256,
               F + F_AIJ, 512, 768LL*512, BB, 0.5f, nullptr, 1, 0,
               HI(B_CAT), LO(B_CAT, SZ_CAT), 0, nullptr, nullptr, 0, 1024, 768LL*1024));

    // ---- G10 (fused K=1024) ----
    launch1(mk(BN, 512, 1024, HI(B_CAT), LO(B_CAT, SZ_CAT), 1024, 0,
               HI(B_WFC), LO(B_WFC, SZ_WFC), 1024, 0,
               F + F_FG, 512, 0, 1, 1.0f, b_f, 0, 1, nullptr, nullptr, 1));

    // ---- G12 (act=2) ----
    launch1(mk(BN, 512, 512, HI(B_CAT), LO(B_CAT, SZ_CAT), 1024, 0,
               HI(B_WM), LO(B_WM, SZ_WM), 512, 0,
               F + F_FG, 512, 0, 1, 1.0f, b_m, 0, 2, HI(B_HB), LO(B_HB, SZ_HB), 0,
               x1, F + F_FG));

    // ---- G13: QKV -> head-split Q/K planes + VT direct (qkv epilogue) ----
    launch1(mk(BN, 1536, 512, HI(B_HB), LO(B_HB, SZ_HB), 512, 0,
               HI(B_WQ), LO(B_WQ, SZ_WQ), 512, 0,
               F, 1536, 0, 1, 1.0f, nullptr, 0, 0, QKVH, nullptr, 0, nullptr, nullptr, 1));

    // ---- fused flash MHSA ----
    flash_mhsa<<<dim3(BB*HH, NN_/128), 256, FL_SMEM>>>(
        QKVH, QKVH + PS, QKVH + 2*PS, QKVH + 3*PS,
        VT, VT + PS, HI(B_HC), LO(B_HC, SZ_HC));

    // ---- G16 ----
    launch1(mk(BN, 512, 512, HI(B_HC), LO(B_HC, SZ_HC), 512, 0,
               HI(B_WP), LO(B_WP, SZ_WP), 512, 0,
               out, 512, 0, 1, 1.0f, b_proj, 0, 0, nullptr, nullptr, 1));
}

// round 16
// speedup vs baseline: 1.0282x; 1.0282x over previous
#include <cuda_runtime.h>
#include <cuda_bf16.h>
#include <math.h>
#include <stdint.h>

// Problem constants
#define BB   16
#define NN_  768
#define FF   512
#define NBB  256
#define HH   8
#define DD   64

typedef __nv_bfloat16 bf16;

__device__ __forceinline__ uint32_t smem_u32(const void* p) {
    uint32_t a;
    asm("{ .reg .u64 t; cvta.to.shared.u64 t, %1; cvt.u32.u64 %0, t; }" : "=r"(a) : "l"(p));
    return a;
}

__device__ __forceinline__ void ldsm4(uint32_t* r, uint32_t addr) {
    asm volatile("ldmatrix.sync.aligned.m8n8.x4.shared.b16 {%0,%1,%2,%3}, [%4];"
        : "=r"(r[0]), "=r"(r[1]), "=r"(r[2]), "=r"(r[3]) : "r"(addr));
}

__device__ __forceinline__ void mma16816(float* c, const uint32_t* a, const uint32_t* b) {
    asm volatile(
        "mma.sync.aligned.m16n8k16.row.col.f32.bf16.bf16.f32 "
        "{%0,%1,%2,%3}, {%4,%5,%6,%7}, {%8,%9}, {%0,%1,%2,%3};"
        : "+f"(c[0]), "+f"(c[1]), "+f"(c[2]), "+f"(c[3])
        : "r"(a[0]), "r"(a[1]), "r"(a[2]), "r"(a[3]), "r"(b[0]), "r"(b[1]));
}

__device__ __forceinline__ void split_hl(float v, bf16& h, bf16& l) {
    h = __float2bfloat16(v);
    l = __float2bfloat16(v - __bfloat162float(h));
}

__device__ __forceinline__ uint32_t packb(bf16 lo16, bf16 hi16) {
    __nv_bfloat162 t; t.x = lo16; t.y = hi16;
    return *(uint32_t*)&t;
}

__device__ __forceinline__ void cp16(uint32_t d, const void* s) {
    asm volatile("cp.async.cg.shared.global [%0], [%1], 16;" :: "r"(d), "l"(s));
}
#define CP_COMMIT() asm volatile("cp.async.commit_group;" ::: "memory")
#define CP_WAIT0()  asm volatile("cp.async.wait_group 0;" ::: "memory")
#define CP_WAIT1()  asm volatile("cp.async.wait_group 1;" ::: "memory")

// ===========================================================================
// Scratch buffers
// ===========================================================================
static const long long F_S1   = 0;
static const long long F_S2   = F_S1  + 16LL*256*768;
static const long long F_S3   = F_S2  + 16LL*768*256;
static const long long F_AIJ  = F_S3  + 16LL*768*256;
static const long long F_FG   = F_AIJ + 12288LL*512;
static const long long F_TOT  = F_FG  + 12288LL*512;

__device__ float g_f32[F_TOT];

#define PS 6291456LL

static const long long B_X1    = 0;                             static const long long SZ_X1    = 12288LL*512;
static const long long B_ZB    = B_X1    + 2*SZ_X1;             static const long long SZ_ZB    = 256LL*512;
static const long long B_WB    = B_ZB    + 2*SZ_ZB;             static const long long SZ_WB    = 1536LL*512;
static const long long B_WI    = B_WB    + 2*SZ_WB;             static const long long SZ_WI    = 1024LL*512;
static const long long B_WJ    = B_WI    + 2*SZ_WI;             static const long long SZ_WJ    = 512LL*512;
static const long long B_WFC   = B_WJ    + 2*SZ_WJ;             static const long long SZ_WFC   = 512LL*1024;
static const long long B_WM    = B_WFC   + 2*SZ_WFC;            static const long long SZ_WM    = 512LL*512;
static const long long B_WQ    = B_WM    + 2*SZ_WM;             static const long long SZ_WQ    = 1536LL*512;
static const long long B_WP    = B_WQ    + 2*SZ_WQ;             static const long long SZ_WP    = 512LL*512;
static const long long B_QKVB  = B_WP    + 2*SZ_WP;             static const long long SZ_QKVB  = 256LL*1536;
static const long long B_KVI   = B_QKVB  + 2*SZ_QKVB;           static const long long SZ_KVI   = 12288LL*1024;
static const long long B_QJ    = B_KVI   + 2*SZ_KVI;            static const long long SZ_QJ    = 12288LL*512;
static const long long B_S1    = B_QJ    + 2*SZ_QJ;             static const long long SZ_S1    = 16LL*256*768;
static const long long B_VIT   = B_S1    + 2*SZ_S1;             static const long long SZ_VIT   = 16LL*512*768;
static const long long B_AIB1  = B_VIT   + 2*SZ_VIT;            static const long long SZ_AIB1  = 16LL*256*512;
static const long long B_AIB1T = B_AIB1  + 2*SZ_AIB1;           static const long long SZ_AIB1T = 16LL*512*256;
static const long long B_VBT   = B_AIB1T + 2*SZ_AIB1T;          static const long long SZ_VBT   = 512LL*256;
static const long long B_S2    = B_VBT   + 2*SZ_VBT;            static const long long SZ_S2    = 16LL*768*256;
static const long long B_S3    = B_S2    + 2*SZ_S2;             static const long long SZ_S3    = 16LL*768*256;
static const long long B_CAT   = B_S3    + 2*SZ_S3;             static const long long SZ_CAT   = 12288LL*1024;
static const long long B_HB    = B_CAT   + 2*SZ_CAT;            static const long long SZ_HB    = 12288LL*512;
static const long long B_QKVH  = B_HB    + 2*SZ_HB;
static const long long B_VT    = B_QKVH  + 6*PS;
static const long long B_HC    = B_VT    + 2*PS;                static const long long SZ_HC    = 12288LL*512;
static const long long B_TOT   = B_HC    + 2*SZ_HC;

__device__ bf16 g_bf[B_TOT];

// ===========================================================================
// GEMM descriptor + multi-GEMM dispatch (wave packing)
// ===========================================================================
#define KT 32
#define SMP 40
#define HALFB  (128 * SMP * 2)
#define STGB   (4 * HALFB)
#define GEMM_SMEM (2 * STGB)

struct GDesc {
    const bf16 *Ahi, *Alo, *Bhi, *Blo;
    int lda, ldb;
    long long sA, sB;
    float* C; int ldc; long long sC;
    float alpha; const float* bias;
    int beta, act;
    bf16 *Chi, *Clo; int wr_f32;
    const float *Gz, *Gf; int qkv;
    int ldco; long long sCo;
    int M, N, K, gx, gy, batch;
};

__device__ __forceinline__ void gemm_body(const GDesc& d, int bxi, int byi, int bzi,
                                          bf16* smbuf, int tid)
{
    const uint32_t sbase = smem_u32(smbuf);
    const int lane = tid & 31, wid = tid >> 5;
    const int m0 = byi * 128, n0 = bxi * 128;
    const int wm = wid & 3, wn = wid >> 2;
    const int m0w = wm * 32, n0w = wn * 64;

    const bf16* Ah = d.Ahi + bzi * d.sA + (size_t)m0 * d.lda;
    const bf16* Al = d.Alo + bzi * d.sA + (size_t)m0 * d.lda;
    const bf16* Bh = d.Bhi + bzi * d.sB + (size_t)n0 * d.ldb;
    const bf16* Bl = d.Blo + bzi * d.sB + (size_t)n0 * d.ldb;

    float acc[2][8][4];
    #pragma unroll
    for (int i = 0; i < 2; ++i)
        #pragma unroll
        for (int j = 0; j < 8; ++j)
            #pragma unroll
            for (int q = 0; q < 4; ++q) acc[i][j][q] = 0.0f;

    const int nk = d.K / KT;
    const int lda = d.lda, ldb = d.ldb;

    auto load_stage = [&](int st, int k0) {
        const uint32_t sb0 = sbase + st * STGB;
        #pragma unroll
        for (int it = 0; it < 2; ++it) {
            int cid = tid + it * 256;
            int row = cid >> 2;
            int c   = (cid & 3) * 8;
            uint32_t off = (uint32_t)(row * SMP + c) * 2;
            cp16(sb0 + off,              Ah + (size_t)row * lda + k0 + c);
            cp16(sb0 + HALFB + off,      Al + (size_t)row * lda + k0 + c);
            cp16(sb0 + 2 * HALFB + off,  Bh + (size_t)row * ldb + k0 + c);
            cp16(sb0 + 3 * HALFB + off,  Bl + (size_t)row * ldb + k0 + c);
        }
    };

    load_stage(0, 0);
    CP_COMMIT();

    for (int i = 0; i < nk; ++i) {
        if (i + 1 < nk) { load_stage((i + 1) & 1, (i + 1) * KT); CP_COMMIT(); }
        if (i + 1 < nk) CP_WAIT1(); else CP_WAIT0();
        __syncthreads();

        const uint32_t sa  = sbase + (i & 1) * STGB;
        const uint32_t sbm = sa + 2 * HALFB;

        #pragma unroll
        for (int kk = 0; kk < 2; ++kk) {
            uint32_t ah[2][4], al[2][4];
            #pragma unroll
            for (int mi = 0; mi < 2; ++mi) {
                uint32_t addr = sa + ((m0w + mi * 16 + (lane & 15)) * SMP
                                      + kk * 16 + (lane >> 4) * 8) * 2;
                ldsm4(ah[mi], addr);
                ldsm4(al[mi], addr + HALFB);
            }
            #pragma unroll
            for (int g = 0; g < 4; ++g) {
                uint32_t bh[4], bl[4];
                int q = lane >> 3;
                int row = n0w + g * 16 + ((q >> 1) << 3) + (lane & 7);
                int kc  = kk * 16 + (q & 1) * 8;
                uint32_t addr = sbm + (row * SMP + kc) * 2;
                ldsm4(bh, addr);
                ldsm4(bl, addr + HALFB);
                #pragma unroll
                for (int mi = 0; mi < 2; ++mi) {
                    mma16816(acc[mi][g * 2 + 0], ah[mi], bh + 0);
                    mma16816(acc[mi][g * 2 + 0], ah[mi], bl + 0);
                    mma16816(acc[mi][g * 2 + 0], al[mi], bh + 0);
                    mma16816(acc[mi][g * 2 + 1], ah[mi], bh + 2);
                    mma16816(acc[mi][g * 2 + 1], ah[mi], bl + 2);
                    mma16816(acc[mi][g * 2 + 1], al[mi], bh + 2);
                }
            }
        }
        __syncthreads();
    }

    const int rb = m0 + m0w + (lane >> 2);
    const int cb = n0 + n0w + (lane & 3) * 2;

    if (d.qkv) {
        #pragma unroll
        for (int mi = 0; mi < 2; ++mi) {
            #pragma unroll
            for (int ni = 0; ni < 8; ++ni) {
                const int col = cb + ni * 8;
                const int t = col >> 9, cw = col & 511;
                const int hh2 = cw >> 6, dd2 = cw & 63;
                bf16* ph = d.Chi + (long long)t * 2 * PS;
                #pragma unroll
                for (int h2 = 0; h2 < 2; ++h2) {
                    const int row = rb + mi * 16 + h2 * 8;
                    const int b2 = row / 768, n2 = row - b2 * 768;
                    size_t ix = ((size_t)((b2 * 8 + hh2) * 768 + n2)) * 64 + dd2;
                    float v0 = acc[mi][ni][h2 * 2 + 0] * d.alpha;
                    float v1 = acc[mi][ni][h2 * 2 + 1] * d.alpha;
                    bf16 h0, l0, h1, l1;
                    split_hl(v0, h0, l0); split_hl(v1, h1, l1);
                    *(uint32_t*)(ph + ix) = packb(h0, h1);
                    *(uint32_t*)(ph + PS + ix) = packb(l0, l1);
                }
            }
        }
        return;
    }

    float* Cb = d.C + bzi * d.sC;
    bf16* Chb = d.Chi ? d.Chi + bzi * d.sCo : nullptr;
    bf16* Clb = d.Clo ? d.Clo + bzi * d.sCo : nullptr;

    #pragma unroll
    for (int mi = 0; mi < 2; ++mi) {
        #pragma unroll
        for (int ni = 0; ni < 8; ++ni) {
            const int col = cb + ni * 8;
            if (col >= d.N) continue;
            float b0 = d.bias ? d.bias[col] : 0.0f;
            float b1 = d.bias ? d.bias[col + 1] : 0.0f;
            #pragma unroll
            for (int h = 0; h < 2; ++h) {
                const int row = rb + mi * 16 + h * 8;
                size_t ix = (size_t)row * d.ldc + col;
                float v0 = acc[mi][ni][h * 2 + 0] * d.alpha + b0;
                float v1 = acc[mi][ni][h * 2 + 1] * d.alpha + b1;
                if (d.beta) { v0 += Cb[ix]; v1 += Cb[ix + 1]; }
                if (d.act == 1) {
                    v0 = 1.0f / (1.0f + __expf(-v0));
                    v1 = 1.0f / (1.0f + __expf(-v1));
                } else if (d.act == 2) {
                    v0 = fmaxf(0.0f, d.Gz[ix] + v0 * d.Gf[ix]);
                    v1 = fmaxf(0.0f, d.Gz[ix + 1] + v1 * d.Gf[ix + 1]);
                }
                if (d.wr_f32) { Cb[ix] = v0; Cb[ix + 1] = v1; }
                if (Chb) {
                    size_t ixo = (size_t)row * d.ldco + col;
                    bf16 hh, ll;
                    split_hl(v0, hh, ll); Chb[ixo] = hh; Clb[ixo] = ll;
                    split_hl(v1, hh, ll); Chb[ixo + 1] = hh; Clb[ixo + 1] = ll;
                }
            }
        }
    }
}

__global__ void __launch_bounds__(256, 2)
mma_multi(GDesc d0, GDesc d1, GDesc d2, int n1, int n2)
{
    extern __shared__ bf16 smbuf[];
    const GDesc& d = (blockIdx.x < (unsigned)n1) ? d0
                   : ((blockIdx.x < (unsigned)n2) ? d1 : d2);
    int local = (blockIdx.x < (unsigned)n1) ? blockIdx.x
              : ((blockIdx.x < (unsigned)n2) ? blockIdx.x - n1 : blockIdx.x - n2);
    int per = d.gx * d.gy;
    int bzi = local / per;
    int rem = local - bzi * per;
    int byi = rem / d.gx;
    int bxi = rem - byi * d.gx;
    gemm_body(d, bxi, byi, bzi, smbuf, threadIdx.x);
}

// ===========================================================================
// Fused flash MHSA — cp.async double-buffered K/V stages (verified R13)
// ===========================================================================
#define QPITCH 72
#define VPITCH 136
#define QPL (128 * QPITCH)
#define VPL (64 * VPITCH)
#define FL_SMEM ((6 * QPL + 4 * VPL) * 2)

__global__ void __launch_bounds__(256)
flash_mhsa(const bf16* __restrict__ Qhp, const bf16* __restrict__ Qlp,
           const bf16* __restrict__ Khp, const bf16* __restrict__ Klp,
           const bf16* __restrict__ VThp, const bf16* __restrict__ VTlp,
           bf16* __restrict__ Ohi, bf16* __restrict__ Olo)
{
    extern __shared__ char sm[];
    const uint32_t base = smem_u32(sm);
    const uint32_t uQ = base;
    const uint32_t uK0 = base + 2 * QPL * 2;
    const uint32_t uV0 = base + 6 * QPL * 2;
    const uint32_t KSTG = 2 * QPL * 2;
    const uint32_t VSTG = 2 * VPL * 2;
    const uint32_t QHALF = QPL * 2;
    const uint32_t VHALF = VPL * 2;

    const int bh = blockIdx.x;
    const int mb = blockIdx.y;
    const int tid = threadIdx.x, lane = tid & 31, wid = tid >> 5;

    const size_t qoff = (size_t)bh * 768 * 64 + (size_t)mb * 128 * 64;
    const size_t koff = (size_t)bh * 768 * 64;
    const size_t voff = (size_t)bh * 64 * 768;

    auto load_kv = [&](int st, int it) {
        const uint32_t uk = uK0 + st * KSTG;
        const uint32_t uv = uV0 + st * VSTG;
        for (int i = tid; i < 1024; i += 256) {
            int r = i >> 3, c = (i & 7) * 8;
            uint32_t dst = uk + (uint32_t)(r * QPITCH + c) * 2;
            cp16(dst,          Khp + koff + (size_t)(it * 128 + r) * 64 + c);
            cp16(dst + QHALF,  Klp + koff + (size_t)(it * 128 + r) * 64 + c);
        }
        for (int i = tid; i < 1024; i += 256) {
            int r = i >> 4, c = (i & 15) * 8;
            uint32_t dst = uv + (uint32_t)(r * VPITCH + c) * 2;
            cp16(dst,          VThp + voff + (size_t)r * 768 + it * 128 + c);
            cp16(dst + VHALF,  VTlp + voff + (size_t)r * 768 + it * 128 + c);
        }
    };

    for (int i = tid; i < 1024; i += 256) {
        int r = i >> 3, c = (i & 7) * 8;
        uint32_t dst = uQ + (uint32_t)(r * QPITCH + c) * 2;
        cp16(dst,          Qhp + qoff + (size_t)r * 64 + c);
        cp16(dst + QHALF,  Qlp + qoff + (size_t)r * 64 + c);
    }
    load_kv(0, 0);
    CP_COMMIT();

    float m_r[2] = {-1e30f, -1e30f};
    float l_r[2] = {0.0f, 0.0f};
    float oacc[8][4];
    #pragma unroll
    for (int j = 0; j < 8; ++j)
        #pragma unroll
        for (int q = 0; q < 4; ++q) oacc[j][q] = 0.0f;

    for (int it = 0; it < 6; ++it) {
        if (it + 1 < 6) { load_kv((it + 1) & 1, it + 1); CP_COMMIT(); }
        if (it + 1 < 6) CP_WAIT1(); else CP_WAIT0();
        __syncthreads();

        const uint32_t uK = uK0 + (it & 1) * KSTG;
        const uint32_t uV = uV0 + (it & 1) * VSTG;

        float sacc[16][4];
        #pragma unroll
        for (int g = 0; g < 16; ++g)
            #pragma unroll
            for (int q = 0; q < 4; ++q) sacc[g][q] = 0.0f;

        #pragma unroll
        for (int kk = 0; kk < 4; ++kk) {
            uint32_t ah[4], al[4];
            uint32_t addr = uQ + ((wid * 16 + (lane & 15)) * QPITCH
                                  + kk * 16 + (lane >> 4) * 8) * 2;
            ldsm4(ah, addr);
            ldsm4(al, addr + QHALF);
            #pragma unroll
            for (int g = 0; g < 8; ++g) {
                uint32_t bh4[4], bl4[4];
                int q = lane >> 3;
                int row = g * 16 + ((q >> 1) << 3) + (lane & 7);
                int kc  = kk * 16 + (q & 1) * 8;
                uint32_t ba = uK + (row * QPITCH + kc) * 2;
                ldsm4(bh4, ba);
                ldsm4(bl4, ba + QHALF);
                mma16816(sacc[g * 2 + 0], ah, bh4 + 0);
                mma16816(sacc[g * 2 + 0], ah, bl4 + 0);
                mma16816(sacc[g * 2 + 0], al, bh4 + 0);
                mma16816(sacc[g * 2 + 1], ah, bh4 + 2);
                mma16816(sacc[g * 2 + 1], ah, bl4 + 2);
                mma16816(sacc[g * 2 + 1], al, bh4 + 2);
            }
        }

        float mx0 = -1e30f, mx1 = -1e30f;
        #pragma unroll
        for (int g = 0; g < 16; ++g) {
            sacc[g][0] *= 0.125f; sacc[g][1] *= 0.125f;
            sacc[g][2] *= 0.125f; sacc[g][3] *= 0.125f;
            mx0 = fmaxf(mx0, fmaxf(sacc[g][0], sacc[g][1]));
            mx1 = fmaxf(mx1, fmaxf(sacc[g][2], sacc[g][3]));
        }
        #pragma unroll
        for (int d = 1; d <= 2; d <<= 1) {
            mx0 = fmaxf(mx0, __shfl_xor_sync(0xffffffffu, mx0, d));
            mx1 = fmaxf(mx1, __shfl_xor_sync(0xffffffffu, mx1, d));
        }
        float mn0 = fmaxf(m_r[0], mx0), mn1 = fmaxf(m_r[1], mx1);
        float al0 = __expf(m_r[0] - mn0), al1 = __expf(m_r[1] - mn1);
        float sum0 = 0.0f, sum1 = 0.0f;
        #pragma unroll
        for (int g = 0; g < 16; ++g) {
            sacc[g][0] = __expf(sacc[g][0] - mn0);
            sacc[g][1] = __expf(sacc[g][1] - mn0);
            sacc[g][2] = __expf(sacc[g][2] - mn1);
            sacc[g][3] = __expf(sacc[g][3] - mn1);
            sum0 += sacc[g][0] + sacc[g][1];
            sum1 += sacc[g][2] + sacc[g][3];
        }
        #pragma unroll
        for (int d = 1; d <= 2; d <<= 1) {
            sum0 += __shfl_xor_sync(0xffffffffu, sum0, d);
            sum1 += __shfl_xor_sync(0xffffffffu, sum1, d);
        }
        l_r[0] = l_r[0] * al0 + sum0;
        l_r[1] = l_r[1] * al1 + sum1;
        m_r[0] = mn0; m_r[1] = mn1;
        #pragma unroll
        for (int j = 0; j < 8; ++j) {
            oacc[j][0] *= al0; oacc[j][1] *= al0;
            oacc[j][2] *= al1; oacc[j][3] *= al1;
        }

        #pragma unroll
        for (int s = 0; s < 8; ++s) {
            uint32_t pah[4], pal[4];
            {
                bf16 h0, l0, h1, l1;
                split_hl(sacc[2*s][0], h0, l0); split_hl(sacc[2*s][1], h1, l1);
                pah[0] = packb(h0, h1); pal[0] = packb(l0, l1);
                split_hl(sacc[2*s][2], h0, l0); split_hl(sacc[2*s][3], h1, l1);
                pah[1] = packb(h0, h1); pal[1] = packb(l0, l1);
                split_hl(sacc[2*s+1][0], h0, l0); split_hl(sacc[2*s+1][1], h1, l1);
                pah[2] = packb(h0, h1); pal[2] = packb(l0, l1);
                split_hl(sacc[2*s+1][2], h0, l0); split_hl(sacc[2*s+1][3], h1, l1);
                pah[3] = packb(h0, h1); pal[3] = packb(l0, l1);
            }
            #pragma unroll
            for (int g = 0; g < 4; ++g) {
                uint32_t bh4[4], bl4[4];
                int q = lane >> 3;
                int row = g * 16 + ((q >> 1) << 3) + (lane & 7);
                int kc  = s * 16 + (q & 1) * 8;
                uint32_t ba = uV + (row * VPITCH + kc) * 2;
                ldsm4(bh4, ba);
                ldsm4(bl4, ba + VHALF);
                mma16816(oacc[g * 2 + 0], pah, bh4 + 0);
                mma16816(oacc[g * 2 + 0], pah, bl4 + 0);
                mma16816(oacc[g * 2 + 0], pal, bh4 + 0);
                mma16816(oacc[g * 2 + 1], pah, bh4 + 2);
                mma16816(oacc[g * 2 + 1], pah, bl4 + 2);
                mma16816(oacc[g * 2 + 1], pal, bh4 + 2);
            }
        }
        __syncthreads();
    }

    const float inv0 = 1.0f / l_r[0], inv1 = 1.0f / l_r[1];
    const int b = bh >> 3, h = bh & 7;
    const int n0g = mb * 128 + wid * 16 + (lane >> 2);
    #pragma unroll
    for (int j = 0; j < 8; ++j) {
        const int d = j * 8 + (lane & 3) * 2;
        {
            size_t ix = ((size_t)(b * 768 + n0g) * 512) + h * 64 + d;
            bf16 h0, l0, h1, l1;
            split_hl(oacc[j][0] * inv0, h0, l0);
            split_hl(oacc[j][1] * inv0, h1, l1);
            *(uint32_t*)(Ohi + ix) = packb(h0, h1);
            *(uint32_t*)(Olo + ix) = packb(l0, l1);
        }
        {
            size_t ix = ((size_t)(b * 768 + n0g + 8) * 512) + h * 64 + d;
            bf16 h0, l0, h1, l1;
            split_hl(oacc[j][2] * inv1, h0, l0);
            split_hl(oacc[j][3] * inv1, h1, l1);
            *(uint32_t*)(Ohi + ix) = packb(h0, h1);
            *(uint32_t*)(Olo + ix) = packb(l0, l1);
        }
    }
}

// ===========================================================================
// Conversion / transform kernels
// ===========================================================================
struct CTable {
    const float* src[3];
    bf16* hi[3];
    bf16* lo[3];
    int lds[3], ldd[3], C[3];
    long long n1, n2;
};

__global__ void conv_batch(CTable ct)
{
    long long i = (long long)blockIdx.x * blockDim.x + threadIdx.x;
    int e; long long local;
    if (i < ct.n1) { e = 0; local = i; }
    else if (i < ct.n2) { e = 1; local = i - ct.n1; }
    else { e = 2; local = i - ct.n2; }
    int c4 = ct.C[e] / 4;
    int r = (int)(local / c4), c = (int)(local % c4) * 4;
    float4 v = *(const float4*)(ct.src[e] + (size_t)r * ct.lds[e] + c);
    bf16 h0, h1, h2, h3, l0, l1, l2, l3;
    split_hl(v.x, h0, l0); split_hl(v.y, h1, l1);
    split_hl(v.z, h2, l2); split_hl(v.w, h3, l3);
    size_t o = (size_t)r * ct.ldd[e] + c;
    bf16* hi = ct.hi[e]; bf16* lo = ct.lo[e];
    hi[o] = h0; hi[o+1] = h1; hi[o+2] = h2; hi[o+3] = h3;
    lo[o] = l0; lo[o+1] = l1; lo[o+2] = l2; lo[o+3] = l3;
}

struct TTable {
    const float* src[8];
    bf16* hi[8];
    bf16* lo[8];
    int lds[8];
    int ldd[8];
    int C[8];
};

__global__ void tconv_batch(TTable tt)
{
    __shared__ float t[32][33];
    const int e = blockIdx.z;
    const int c0 = blockIdx.x * 32;
    if (c0 >= tt.C[e]) return;
    const float* s = tt.src[e];
    const int lds = tt.lds[e], ldd = tt.ldd[e];
    const int r0 = blockIdx.y * 32;
    int tx = threadIdx.x, ty = threadIdx.y;
    #pragma unroll
    for (int i = 0; i < 32; i += 8) {
        int r = r0 + ty + i, c = c0 + tx;
        t[ty + i][tx] = s[(size_t)r * lds + c];
    }
    __syncthreads();
    bf16* hb = tt.hi[e];
    bf16* lb = tt.lo[e];
    #pragma unroll
    for (int i = 0; i < 32; i += 8) {
        int c = c0 + ty + i, r = r0 + tx;
        bf16 h, l; split_hl(t[tx][ty + i], h, l);
        hb[(size_t)c * ldd + r] = h;
        lb[(size_t)c * ldd + r] = l;
    }
}

__global__ void tconv_bf(const bf16* __restrict__ sh, const bf16* __restrict__ sl,
                         int lds, long long sS,
                         bf16* __restrict__ dh, bf16* __restrict__ dl,
                         int ldd, long long sD, int R, int C)
{
    __shared__ uint32_t t[32][33];
    const bf16* ph = sh + blockIdx.z * sS;
    const bf16* pl = sl + blockIdx.z * sS;
    int r0 = blockIdx.y * 32, c0 = blockIdx.x * 32;
    int tx = threadIdx.x, ty = threadIdx.y;
    #pragma unroll
    for (int i = 0; i < 32; i += 8) {
        int r = r0 + ty + i, c = c0 + tx;
        t[ty + i][tx] = packb(ph[(size_t)r * lds + c], pl[(size_t)r * lds + c]);
    }
    __syncthreads();
    bf16* hb = dh + blockIdx.z * sD;
    bf16* lb = dl + blockIdx.z * sD;
    #pragma unroll
    for (int i = 0; i < 32; i += 8) {
        int c = c0 + ty + i, r = r0 + tx;
        uint32_t u = t[tx][ty + i];
        __nv_bfloat162 p = *(__nv_bfloat162*)&u;
        hb[(size_t)c * ldd + r] = p.x;
        lb[(size_t)c * ldd + r] = p.y;
    }
}

// merged v_i (z=0..15) + v_b (z=16) transpose
__global__ void tconv_vbvi(const bf16* __restrict__ kvi_h, const bf16* __restrict__ kvi_l,
                           bf16* __restrict__ vit_h, bf16* __restrict__ vit_l,
                           const bf16* __restrict__ qkvb_h, const bf16* __restrict__ qkvb_l,
                           bf16* __restrict__ vbt_h, bf16* __restrict__ vbt_l)
{
    __shared__ uint32_t t[32][33];
    const int z = blockIdx.z;
    const bf16 *ph, *pl; bf16 *hb, *lb;
    int lds, ldd, R;
    if (z < 16) {
        ph = kvi_h + (size_t)z * 768 * 1024; pl = kvi_l + (size_t)z * 768 * 1024;
        hb = vit_h + (size_t)z * 512 * 768;  lb = vit_l + (size_t)z * 512 * 768;
        lds = 1024; ldd = 768; R = 768;
    } else {
        ph = qkvb_h; pl = qkvb_l;
        hb = vbt_h;  lb = vbt_l;
        lds = 1536; ldd = 256; R = 256;
    }
    int r0 = blockIdx.y * 32, c0 = blockIdx.x * 32;
    if (r0 >= R) return;
    int tx = threadIdx.x, ty = threadIdx.y;
    #pragma unroll
    for (int i = 0; i < 32; i += 8) {
        int r = r0 + ty + i, c = c0 + tx;
        t[ty + i][tx] = packb(ph[(size_t)r * lds + c], pl[(size_t)r * lds + c]);
    }
    __syncthreads();
    #pragma unroll
    for (int i = 0; i < 32; i += 8) {
        int c = c0 + ty + i, r = r0 + tx;
        uint32_t u = t[tx][ty + i];
        __nv_bfloat162 p = *(__nv_bfloat162*)&u;
        hb[(size_t)c * ldd + r] = p.x;
        lb[(size_t)c * ldd + r] = p.y;
    }
}

__device__ __forceinline__ void softmax_body(const float* p, bf16* ph, bf16* pl, int L, int t)
{
    __shared__ float red[256];
    const int nv = L >> 8;
    float v[3];
    float mx = -1e30f;
    for (int j = 0; j < nv; ++j) {
        v[j] = p[t + (j << 8)];
        mx = fmaxf(mx, v[j]);
    }
    red[t] = mx; __syncthreads();
    for (int s = 128; s > 0; s >>= 1) { if (t < s) red[t] = fmaxf(red[t], red[t + s]); __syncthreads(); }
    mx = red[0]; __syncthreads();

    float e[3];
    float sum = 0.0f;
    for (int j = 0; j < nv; ++j) {
        e[j] = __expf(v[j] - mx);
        sum += e[j];
    }
    red[t] = sum; __syncthreads();
    for (int s = 128; s > 0; s >>= 1) { if (t < s) red[t] += red[t + s]; __syncthreads(); }
    const float inv = 1.0f / red[0];
    for (int j = 0; j < nv; ++j) {
        float w = e[j] * inv;
        bf16 h, l; split_hl(w, h, l);
        ph[t + (j << 8)] = h; pl[t + (j << 8)] = l;
    }
}

__global__ void __launch_bounds__(256)
softmax_hilo(const float* __restrict__ src, bf16* __restrict__ hi, bf16* __restrict__ lo, int L)
{
    softmax_body(src + (size_t)blockIdx.x * L, hi + (size_t)blockIdx.x * L,
                 lo + (size_t)blockIdx.x * L, L, threadIdx.x);
}

__global__ void __launch_bounds__(256)
softmax2(const float* __restrict__ s1, bf16* __restrict__ h1, bf16* __restrict__ l1,
         int L1, int nb1,
         const float* __restrict__ s2, bf16* __restrict__ h2, bf16* __restrict__ l2, int L2)
{
    if (blockIdx.x < (unsigned)nb1) {
        size_t o = (size_t)blockIdx.x * L1;
        softmax_body(s1 + o, h1 + o, l1 + o, L1, threadIdx.x);
    } else {
        size_t o = (size_t)(blockIdx.x - nb1) * L2;
        softmax_body(s2 + o, h2 + o, l2 + o, L2, threadIdx.x);
    }
}

// ===========================================================================
// Host side
// ===========================================================================
static GDesc mk(int M, int N, int K,
                const bf16* Ah, const bf16* Al, int lda, long long sA,
                const bf16* Bh, const bf16* Bl, int ldb, long long sB,
                float* C, int ldc, long long sC, int batch,
                float alpha, const float* bias, int beta, int act,
                bf16* Chi, bf16* Clo, int wr_f32,
                const float* Gz = nullptr, const float* Gf = nullptr, int qkv = 0,
                int ldco = -1, long long sCo = -1)
{
    GDesc d;
    d.Ahi = Ah; d.Alo = Al; d.Bhi = Bh; d.Blo = Bl;
    d.lda = lda; d.ldb = ldb; d.sA = sA; d.sB = sB;
    d.C = C; d.ldc = ldc; d.sC = sC;
    d.alpha = alpha; d.bias = bias; d.beta = beta; d.act = act;
    d.Chi = Chi; d.Clo = Clo; d.wr_f32 = wr_f32;
    d.Gz = Gz; d.Gf = Gf; d.qkv = qkv;
    d.ldco = (ldco < 0) ? ldc : ldco;
    d.sCo = (sCo < 0) ? sC : sCo;
    d.M = M; d.N = N; d.K = K;
    d.gx = (N + 127) / 128; d.gy = M / 128; d.batch = batch;
    return d;
}
static inline int nblk(const GDesc& d) { return d.gx * d.gy * d.batch; }

static void launch1(const GDesc& a) {
    int n = nblk(a);
    mma_multi<<<n, 256, GEMM_SMEM>>>(a, a, a, n, n);
}
static void launch2(const GDesc& a, const GDesc& b) {
    int na = nblk(a), nb = nblk(b);
    mma_multi<<<na + nb, 256, GEMM_SMEM>>>(a, b, b, na, na + nb);
}
static void launch3(const GDesc& a, const GDesc& b, const GDesc& c) {
    int na = nblk(a), nb = nblk(b), nc = nblk(c);
    mma_multi<<<na + nb + nc, 256, GEMM_SMEM>>>(a, b, c, na, na + nb);
}

extern "C" void kernel_launch(void* const* d_in, const int* in_sizes, int n_in,
                              void* d_out, int out_size)
{
    (void)in_sizes; (void)n_in; (void)out_size;

    cudaFuncSetAttribute(flash_mhsa, cudaFuncAttributeMaxDynamicSharedMemorySize, FL_SMEM);
    cudaFuncSetAttribute(mma_multi, cudaFuncAttributeMaxDynamicSharedMemorySize, GEMM_SMEM);

    float* F = nullptr; bf16* Bf = nullptr;
    cudaGetSymbolAddress((void**)&F, g_f32);
    cudaGetSymbolAddress((void**)&Bf, g_bf);

    const float* x1     = (const float*)d_in[0];
    const float* x2     = (const float*)d_in[1];
    const float* zb     = (const float*)d_in[2];
    const float* Wqkv_i = (const float*)d_in[3];
    const float* Wqkv_j = (const float*)d_in[4];
    const float* Wqkv_b = (const float*)d_in[5];
    const float* W_f    = (const float*)d_in[6];
    const float* b_f    = (const float*)d_in[7];
    const float* W_m    = (const float*)d_in[8];
    const float* b_m    = (const float*)d_in[9];
    const float* W_QKV  = (const float*)d_in[10];
    const float* W_proj = (const float*)d_in[11];
    const float* b_proj = (const float*)d_in[12];
    float* out = (float*)d_out;

    const float scale = 0.044194173824159216f;
    const int   BN    = BB * NN_;

    #define HI(X) (Bf + (X))
    #define LO(X, SZ) (Bf + (X) + (SZ))

    bf16* QKVH = Bf + B_QKVH;
    bf16* VT   = Bf + B_VT;

    // ---- input conversions ----
    {
        CTable ct;
        ct.src[0] = x1; ct.hi[0] = HI(B_X1);        ct.lo[0] = LO(B_X1, SZ_X1);        ct.lds[0] = 512; ct.ldd[0] = 512;  ct.C[0] = 512;
        ct.src[1] = x2; ct.hi[1] = HI(B_CAT) + 512; ct.lo[1] = LO(B_CAT, SZ_CAT) + 512; ct.lds[1] = 512; ct.ldd[1] = 1024; ct.C[1] = 512;
        ct.src[2] = zb; ct.hi[2] = HI(B_ZB);        ct.lo[2] = LO(B_ZB, SZ_ZB);        ct.lds[2] = 512; ct.ldd[2] = 512;  ct.C[2] = 512;
        ct.n1 = 12288LL * 128;
        ct.n2 = ct.n1 + 12288LL * 128;
        long long tot = ct.n2 + 256LL * 128;
        conv_batch<<<(unsigned)((tot + 255) / 256), 256>>>(ct);
    }

    // ---- all weight transposes in ONE batched launch ----
    {
        TTable tt;
        tt.src[0] = Wqkv_b;           tt.hi[0] = HI(B_WB);        tt.lo[0] = LO(B_WB, SZ_WB);         tt.lds[0] = 1536; tt.ldd[0] = 512;  tt.C[0] = 1536;
        tt.src[1] = Wqkv_i + 512;     tt.hi[1] = HI(B_WI);        tt.lo[1] = LO(B_WI, SZ_WI);         tt.lds[1] = 1536; tt.ldd[1] = 512;  tt.C[1] = 1024;
        tt.src[2] = Wqkv_j;           tt.hi[2] = HI(B_WJ);        tt.lo[2] = LO(B_WJ, SZ_WJ);         tt.lds[2] = 1536; tt.ldd[2] = 512;  tt.C[2] = 512;
        tt.src[3] = W_f;              tt.hi[3] = HI(B_WFC);       tt.lo[3] = LO(B_WFC, SZ_WFC);       tt.lds[3] = 512;  tt.ldd[3] = 1024; tt.C[3] = 512;
        tt.src[4] = W_f + 512LL*512;  tt.hi[4] = HI(B_WFC) + 512; tt.lo[4] = LO(B_WFC, SZ_WFC) + 512; tt.lds[4] = 512;  tt.ldd[4] = 1024; tt.C[4] = 512;
        tt.src[5] = W_m;              tt.hi[5] = HI(B_WM);        tt.lo[5] = LO(B_WM, SZ_WM);         tt.lds[5] = 512;  tt.ldd[5] = 512;  tt.C[5] = 512;
        tt.src[6] = W_QKV;            tt.hi[6] = HI(B_WQ);        tt.lo[6] = LO(B_WQ, SZ_WQ);         tt.lds[6] = 1536; tt.ldd[6] = 512;  tt.C[6] = 1536;
        tt.src[7] = W_proj;           tt.hi[7] = HI(B_WP);        tt.lo[7] = LO(B_WP, SZ_WP);         tt.lds[7] = 512;  tt.ldd[7] = 512;  tt.C[7] = 512;
        tconv_batch<<<dim3(1536/32, 512/32, 8), dim3(32, 8)>>>(tt);
    }

    dim3 tb(32, 8);

    // ---- Group A: G1 + G2 + G3 ----
    GDesc g1 = mk(256, 1536, 512, HI(B_ZB), LO(B_ZB, SZ_ZB), 512, 0, HI(B_WB), LO(B_WB, SZ_WB), 512, 0,
                  F, 1536, 0, 1, 0.2f, nullptr, 0, 0, HI(B_QKVB), LO(B_QKVB, SZ_QKVB), 0);
    GDesc g2 = mk(BN, 1024, 512, HI(B_X1), LO(B_X1, SZ_X1), 512, 0, HI(B_WI), LO(B_WI, SZ_WI), 512, 0,
                  F, 1024, 0, 1, 1.0f, nullptr, 0, 0, HI(B_KVI), LO(B_KVI, SZ_KVI), 0);
    GDesc g3 = mk(BN, 512, 512, HI(B_CAT) + 512, LO(B_CAT, SZ_CAT) + 512, 1024, 0,
                  HI(B_WJ), LO(B_WJ, SZ_WJ), 512, 0,
                  F, 512, 0, 1, 1.0f, nullptr, 0, 0, HI(B_QJ), LO(B_QJ, SZ_QJ), 0);
    launch3(g2, g3, g1);

    // ---- merged v_b + v_i transposes ----
    tconv_vbvi<<<dim3(16, 24, 17), tb>>>(
        HI(B_KVI) + 512, LO(B_KVI, SZ_KVI) + 512, HI(B_VIT), LO(B_VIT, SZ_VIT),
        HI(B_QKVB) + 1024, LO(B_QKVB, SZ_QKVB) + 1024, HI(B_VBT), LO(B_VBT, SZ_VBT));

    // ---- Group B: G4 + G6 ----
    GDesc g4 = mk(256, 768, 512, HI(B_QKVB), LO(B_QKVB, SZ_QKVB), 1536, 0,
                  HI(B_KVI), LO(B_KVI, SZ_KVI), 1024, 768LL*1024,
                  F + F_S1, 768, 256LL*768, BB, scale, nullptr, 0, 0, nullptr, nullptr, 1);
    GDesc g6 = mk(768, 256, 512, HI(B_QJ), LO(B_QJ, SZ_QJ), 512, 768LL*512,
                  HI(B_QKVB) + 512, LO(B_QKVB, SZ_QKVB) + 512, 1536, 0,
                  F + F_S2, 256, 768LL*256, BB, scale, nullptr, 0, 0, nullptr, nullptr, 1);
    launch2(g4, g6);

    // ---- merged softmax S1 + S2 ----
    softmax2<<<BB*256 + BB*768, 256>>>(
        F + F_S1, HI(B_S1), LO(B_S1, SZ_S1), 768, BB*256,
        F + F_S2, HI(B_S2), LO(B_S2, SZ_S2), 256);

    // ---- G5 alone, then AIB1T transpose ----
    GDesc g5 = mk(256, 512, 768, HI(B_S1), LO(B_S1, SZ_S1), 768, 256LL*768,
                  HI(B_VIT), LO(B_VIT, SZ_VIT), 768, 512LL*768,
                  F, 512, 256LL*512, BB, 1.0f, nullptr, 0, 0, HI(B_AIB1), LO(B_AIB1, SZ_AIB1), 0);
    launch1(g5);

    tconv_bf<<<dim3(512/32, 256/32, BB), tb>>>(HI(B_AIB1), LO(B_AIB1, SZ_AIB1), 512, 256LL*512,
        HI(B_AIB1T), LO(B_AIB1T, SZ_AIB1T), 256, 512LL*256, 256, 512);

    // ---- G7 + G8 packed (independent: G7 needs softmax2, G8 needs G5) ----
    GDesc g7 = mk(768, 512, 256, HI(B_S2), LO(B_S2, SZ_S2), 256, 768LL*256,
                  HI(B_VBT), LO(B_VBT, SZ_VBT), 256, 0,
                  F + F_AIJ, 512, 768LL*512, BB, 0.5f, nullptr, 0, 0, nullptr, nullptr, 1);
    GDesc g8 = mk(768, 256, 512, HI(B_X1), LO(B_X1, SZ_X1), 512, 768LL*512,
                  HI(B_AIB1), LO(B_AIB1, SZ_AIB1), 512, 256LL*512,
                  F + F_S3, 256, 768LL*256, BB, scale, nullptr, 0, 0, nullptr, nullptr, 1);
    launch2(g7, g8);

    softmax_hilo<<<BB*768, 256>>>(F + F_S3, HI(B_S3), LO(B_S3, SZ_S3), 256);

    // ---- G9 ----
    launch1(mk(768, 512, 256, HI(B_S3), LO(B_S3, SZ_S3), 256, 768LL*256,
               HI(B_AIB1T), LO(B_AIB1T, SZ_AIB1T), 256, 512LL*256,
               F + F_AIJ, 512, 768LL*512, BB, 0.5f, nullptr, 1, 0,
               HI(B_CAT), LO(B_CAT, SZ_CAT), 0, nullptr, nullptr, 0, 1024, 768LL*1024));

    // ---- G10 (fused K=1024) ----
    launch1(mk(BN, 512, 1024, HI(B_CAT), LO(B_CAT, SZ_CAT), 1024, 0,
               HI(B_WFC), LO(B_WFC, SZ_WFC), 1024, 0,
               F + F_FG, 512, 0, 1, 1.0f, b_f, 0, 1, nullptr, nullptr, 1));

    // ---- G12 (act=2) ----
    launch1(mk(BN, 512, 512, HI(B_CAT), LO(B_CAT, SZ_CAT), 1024, 0,
               HI(B_WM), LO(B_WM, SZ_WM), 512, 0,
               F + F_FG, 512, 0, 1, 1.0f, b_m, 0, 2, HI(B_HB), LO(B_HB, SZ_HB), 0,
               x1, F + F_FG));

    // ---- G13: QKV -> head-split planes ----
    launch1(mk(BN, 1536, 512, HI(B_HB), LO(B_HB, SZ_HB), 512, 0,
               HI(B_WQ), LO(B_WQ, SZ_WQ), 512, 0,
               F, 1536, 0, 1, 1.0f, nullptr, 0, 0, QKVH, nullptr, 0, nullptr, nullptr, 1));

    // ---- V^T per head ----
    tconv_bf<<<dim3(64/32, 768/32, BB*HH), tb>>>(QKVH + 4*PS, QKVH + 5*PS, 64, 768LL*64,
        VT, VT + PS, 768, 64LL*768, 768, 64);

    // ---- fused flash MHSA (cp.async pipelined) ----
    flash_mhsa<<<dim3(BB*HH, NN_/128), 256, FL_SMEM>>>(
        QKVH, QKVH + PS, QKVH + 2*PS, QKVH + 3*PS,
        VT, VT + PS, HI(B_HC), LO(B_HC, SZ_HC));

    // ---- G16 ----
    launch1(mk(BN, 512, 512, HI(B_HC), LO(B_HC, SZ_HC), 512, 0,
               HI(B_WP), LO(B_WP, SZ_WP), 512, 0,
               out, 512, 0, 1, 1.0f, b_proj, 0, 0, nullptr, nullptr, 1));
}